// round 1
// baseline (speedup 1.0000x reference)
#include <cuda_runtime.h>
#include <math.h>

#define T_C 8192
#define E_C 1024

// ---------------- scratch (device globals; no allocations allowed) ----------
__device__ float g_kx[T_C * E_C];
__device__ float g_vx[T_C * E_C];
__device__ float g_rx[T_C * E_C];
__device__ float g_k [T_C * E_C];
__device__ float g_v [T_C * E_C];
__device__ float g_r [T_C * E_C];
__device__ float g_rwkv[T_C * E_C];

// ---------------- token-shift mix -------------------------------------------
__global__ void mix_kernel(const float* __restrict__ x,
                           const float* __restrict__ sx,
                           const float* __restrict__ tmk,
                           const float* __restrict__ tmv,
                           const float* __restrict__ tmr) {
    int idx = blockIdx.x * blockDim.x + threadIdx.x;  // over T*E/4 float4s
    const int n4 = T_C * E_C / 4;
    if (idx >= n4) return;
    const int E4 = E_C / 4;
    int e4 = idx % E4;
    int t  = idx / E4;

    float4 xv = reinterpret_cast<const float4*>(x)[idx];
    float4 sv = (t == 0) ? reinterpret_cast<const float4*>(sx)[e4]
                         : reinterpret_cast<const float4*>(x)[idx - E4];
    float4 mk = reinterpret_cast<const float4*>(tmk)[e4];
    float4 mv = reinterpret_cast<const float4*>(tmv)[e4];
    float4 mr = reinterpret_cast<const float4*>(tmr)[e4];

    float4 o;
    o.x = xv.x * mk.x + sv.x * (1.f - mk.x);
    o.y = xv.y * mk.y + sv.y * (1.f - mk.y);
    o.z = xv.z * mk.z + sv.z * (1.f - mk.z);
    o.w = xv.w * mk.w + sv.w * (1.f - mk.w);
    reinterpret_cast<float4*>(g_kx)[idx] = o;

    o.x = xv.x * mv.x + sv.x * (1.f - mv.x);
    o.y = xv.y * mv.y + sv.y * (1.f - mv.y);
    o.z = xv.z * mv.z + sv.z * (1.f - mv.z);
    o.w = xv.w * mv.w + sv.w * (1.f - mv.w);
    reinterpret_cast<float4*>(g_vx)[idx] = o;

    o.x = xv.x * mr.x + sv.x * (1.f - mr.x);
    o.y = xv.y * mr.y + sv.y * (1.f - mr.y);
    o.z = xv.z * mr.z + sv.z * (1.f - mr.z);
    o.w = xv.w * mr.w + sv.w * (1.f - mr.w);
    reinterpret_cast<float4*>(g_rx)[idx] = o;
}

// ---------------- SGEMM: C[M,N] = A[M,K] @ B[K,N]  (+ epilogue) --------------
// MODE 0: plain, MODE 1: sigmoid, MODE 2: residual add (C = R + acc)
template <int MODE>
__global__ __launch_bounds__(256)
void sgemm_kernel(const float* __restrict__ A,
                  const float* __restrict__ B,
                  float* __restrict__ C,
                  const float* __restrict__ R) {
    constexpr int BM = 128, BN = 128, BK = 8, TM = 8, TN = 8;
    const int K = E_C, N = E_C;

    __shared__ float As[BK][BM];
    __shared__ float Bs[BK][BN];

    const int tid  = threadIdx.x;
    const int bRow = blockIdx.y;
    const int bCol = blockIdx.x;

    // global->smem load mapping
    const int aRow = tid >> 1;           // 0..127
    const int aCol = (tid & 1) * 4;      // 0 or 4
    const int bR   = tid >> 5;           // 0..7
    const int bC   = (tid & 31) * 4;     // 0..124

    // compute mapping: 16x16 threads, each 8x8
    const int tr = tid >> 4;             // 0..15
    const int tc = tid & 15;             // 0..15

    const float* Aptr = A + (size_t)(bRow * BM) * K;
    const float* Bptr = B + bCol * BN;

    float acc[TM][TN];
    #pragma unroll
    for (int i = 0; i < TM; i++)
        #pragma unroll
        for (int j = 0; j < TN; j++) acc[i][j] = 0.f;

    for (int kt = 0; kt < K; kt += BK) {
        float4 a4 = *reinterpret_cast<const float4*>(Aptr + (size_t)aRow * K + kt + aCol);
        As[aCol + 0][aRow] = a4.x;
        As[aCol + 1][aRow] = a4.y;
        As[aCol + 2][aRow] = a4.z;
        As[aCol + 3][aRow] = a4.w;
        float4 b4 = *reinterpret_cast<const float4*>(Bptr + (size_t)(kt + bR) * N + bC);
        *reinterpret_cast<float4*>(&Bs[bR][bC]) = b4;
        __syncthreads();

        #pragma unroll
        for (int kk = 0; kk < BK; kk++) {
            float regM[TM], regN[TN];
            *reinterpret_cast<float4*>(&regM[0]) = *reinterpret_cast<const float4*>(&As[kk][tr * TM + 0]);
            *reinterpret_cast<float4*>(&regM[4]) = *reinterpret_cast<const float4*>(&As[kk][tr * TM + 4]);
            *reinterpret_cast<float4*>(&regN[0]) = *reinterpret_cast<const float4*>(&Bs[kk][tc * TN + 0]);
            *reinterpret_cast<float4*>(&regN[4]) = *reinterpret_cast<const float4*>(&Bs[kk][tc * TN + 4]);
            #pragma unroll
            for (int i = 0; i < TM; i++)
                #pragma unroll
                for (int j = 0; j < TN; j++)
                    acc[i][j] += regM[i] * regN[j];
        }
        __syncthreads();
    }

    // epilogue
    #pragma unroll
    for (int i = 0; i < TM; i++) {
        const size_t row = (size_t)(bRow * BM + tr * TM + i);
        #pragma unroll
        for (int jj = 0; jj < TN; jj += 4) {
            const size_t idx = row * N + bCol * BN + tc * TN + jj;
            float4 v;
            v.x = acc[i][jj + 0]; v.y = acc[i][jj + 1];
            v.z = acc[i][jj + 2]; v.w = acc[i][jj + 3];
            if (MODE == 1) {
                v.x = 1.f / (1.f + __expf(-v.x));
                v.y = 1.f / (1.f + __expf(-v.y));
                v.z = 1.f / (1.f + __expf(-v.z));
                v.w = 1.f / (1.f + __expf(-v.w));
            } else if (MODE == 2) {
                float4 r4 = *reinterpret_cast<const float4*>(R + idx);
                v.x += r4.x; v.y += r4.y; v.z += r4.z; v.w += r4.w;
            }
            *reinterpret_cast<float4*>(C + idx) = v;
        }
    }
}

// ---------------- WKV sequential scan ---------------------------------------
// 1024 independent channels, one thread each. Double-buffered chunk prefetch.
__global__ void scan_kernel(const float* __restrict__ aa_in,
                            const float* __restrict__ bb_in,
                            const float* __restrict__ pp_in,
                            const float* __restrict__ tf_in,
                            const float* __restrict__ td_in,
                            const float* __restrict__ x,
                            float* __restrict__ out_tail,
                            int write_tail) {
    const int e = blockIdx.x * blockDim.x + threadIdx.x;
    if (e >= E_C) return;

    float aa = aa_in[e], bb = bb_in[e], pp = pp_in[e];
    const float tf  = tf_in[e];
    const float dec = -__expf(td_in[e]);

    constexpr int U = 16;
    constexpr int NC = T_C / U;
    float kb[2][U], vb[2][U], rb[2][U];

    // prime buffer 0
    #pragma unroll
    for (int i = 0; i < U; i++) {
        kb[0][i] = g_k[(size_t)i * E_C + e];
        vb[0][i] = g_v[(size_t)i * E_C + e];
        rb[0][i] = g_r[(size_t)i * E_C + e];
    }

    for (int c = 0; c < NC; c++) {
        const int cur = c & 1;
        if (c + 1 < NC) {
            const size_t base = (size_t)(c + 1) * U * E_C + e;
            #pragma unroll
            for (int i = 0; i < U; i++) {
                kb[cur ^ 1][i] = g_k[base + (size_t)i * E_C];
                vb[cur ^ 1][i] = g_v[base + (size_t)i * E_C];
                rb[cur ^ 1][i] = g_r[base + (size_t)i * E_C];
            }
        }
        #pragma unroll
        for (int i = 0; i < U; i++) {
            const int t = c * U + i;
            const float kk = kb[cur][i];
            const float vv = vb[cur][i];

            // output: p = max(pp, ww); one of the two exps is exactly 1
            const float ww = tf + kk;
            const float d  = pp - ww;
            const float m  = __expf(-fabsf(d));
            const float e1 = (d >= 0.f) ? 1.f : m;
            const float e2 = (d >= 0.f) ? m : 1.f;
            const float w  = __fdividef(e1 * aa + e2 * vv, e1 * bb + e2);
            g_rwkv[(size_t)t * E_C + e] = rb[cur][i] * w;

            // state update
            const float ww2 = dec + pp;
            const float d2  = ww2 - kk;
            const float m2  = __expf(-fabsf(d2));
            const float e1b = (d2 >= 0.f) ? 1.f : m2;
            const float e2b = (d2 >= 0.f) ? m2 : 1.f;
            aa = e1b * aa + e2b * vv;
            bb = e1b * bb + e2b;
            pp = (d2 >= 0.f) ? ww2 : kk;
        }
    }

    if (write_tail) {
        out_tail[(size_t)T_C * E_C + 0 * E_C + e] = x[(size_t)(T_C - 1) * E_C + e];
        out_tail[(size_t)T_C * E_C + 1 * E_C + e] = aa;
        out_tail[(size_t)T_C * E_C + 2 * E_C + e] = bb;
        out_tail[(size_t)T_C * E_C + 3 * E_C + e] = pp;
    }
}

// ---------------- launch -----------------------------------------------------
extern "C" void kernel_launch(void* const* d_in, const int* in_sizes, int n_in,
                              void* d_out, int out_size) {
    const float* x   = (const float*)d_in[0];
    const float* sx  = (const float*)d_in[1];
    const float* aa  = (const float*)d_in[2];
    const float* bb  = (const float*)d_in[3];
    const float* pp  = (const float*)d_in[4];
    const float* tf  = (const float*)d_in[5];
    const float* td  = (const float*)d_in[6];
    const float* tmk = (const float*)d_in[7];
    const float* tmv = (const float*)d_in[8];
    const float* tmr = (const float*)d_in[9];
    const float* Wk  = (const float*)d_in[10];
    const float* Wv  = (const float*)d_in[11];
    const float* Wr  = (const float*)d_in[12];
    const float* Wo  = (const float*)d_in[13];
    float* out = (float*)d_out;

    float *p_kx, *p_vx, *p_rx, *p_k, *p_v, *p_r, *p_rwkv;
    cudaGetSymbolAddress((void**)&p_kx,   g_kx);
    cudaGetSymbolAddress((void**)&p_vx,   g_vx);
    cudaGetSymbolAddress((void**)&p_rx,   g_rx);
    cudaGetSymbolAddress((void**)&p_k,    g_k);
    cudaGetSymbolAddress((void**)&p_v,    g_v);
    cudaGetSymbolAddress((void**)&p_r,    g_r);
    cudaGetSymbolAddress((void**)&p_rwkv, g_rwkv);

    // 1) token-shift mixes
    {
        const int n4 = T_C * E_C / 4;
        mix_kernel<<<(n4 + 255) / 256, 256>>>(x, sx, tmk, tmv, tmr);
    }

    // 2) k, v, r GEMMs
    dim3 ggrid(E_C / 128, T_C / 128);
    sgemm_kernel<0><<<ggrid, 256>>>(p_kx, Wk, p_k, nullptr);
    sgemm_kernel<0><<<ggrid, 256>>>(p_vx, Wv, p_v, nullptr);
    sgemm_kernel<1><<<ggrid, 256>>>(p_rx, Wr, p_r, nullptr);

    // 3) WKV scan (writes rwkv = r * wkv, plus tail state outputs)
    const int write_tail = (out_size >= T_C * E_C + 4 * E_C) ? 1 : 0;
    scan_kernel<<<32, 32>>>(aa, bb, pp, tf, td, x, out, write_tail);

    // 4) out = x + rwkv @ Wo
    sgemm_kernel<2><<<ggrid, 256>>>(p_rwkv, Wo, out, x);
}

// round 2
// speedup vs baseline: 1.6352x; 1.6352x over previous
#include <cuda_runtime.h>
#include <math.h>

#define T_C 8192
#define E_C 1024
#define SEG 64
#define SEGL (T_C / SEG)   // 128

// ---------------- scratch (device globals; no allocations allowed) ----------
__device__ float g_kx[T_C * E_C];
__device__ float g_vx[T_C * E_C];
__device__ float g_rx[T_C * E_C];
__device__ float g_k [T_C * E_C];
__device__ float g_v [T_C * E_C];
__device__ float g_r [T_C * E_C];
__device__ float g_rwkv[T_C * E_C];
// segment summaries / initial states
__device__ float g_ua[SEG * E_C];
__device__ float g_ub[SEG * E_C];
__device__ float g_up[SEG * E_C];
__device__ float g_sa[SEG * E_C];
__device__ float g_sb[SEG * E_C];
__device__ float g_sp[SEG * E_C];

// ---------------- token-shift mix -------------------------------------------
__global__ void mix_kernel(const float* __restrict__ x,
                           const float* __restrict__ sx,
                           const float* __restrict__ tmk,
                           const float* __restrict__ tmv,
                           const float* __restrict__ tmr) {
    int idx = blockIdx.x * blockDim.x + threadIdx.x;
    const int n4 = T_C * E_C / 4;
    if (idx >= n4) return;
    const int E4 = E_C / 4;
    int e4 = idx % E4;
    int t  = idx / E4;

    float4 xv = reinterpret_cast<const float4*>(x)[idx];
    float4 sv = (t == 0) ? reinterpret_cast<const float4*>(sx)[e4]
                         : reinterpret_cast<const float4*>(x)[idx - E4];
    float4 mk = reinterpret_cast<const float4*>(tmk)[e4];
    float4 mv = reinterpret_cast<const float4*>(tmv)[e4];
    float4 mr = reinterpret_cast<const float4*>(tmr)[e4];

    float4 o;
    o.x = xv.x * mk.x + sv.x * (1.f - mk.x);
    o.y = xv.y * mk.y + sv.y * (1.f - mk.y);
    o.z = xv.z * mk.z + sv.z * (1.f - mk.z);
    o.w = xv.w * mk.w + sv.w * (1.f - mk.w);
    reinterpret_cast<float4*>(g_kx)[idx] = o;

    o.x = xv.x * mv.x + sv.x * (1.f - mv.x);
    o.y = xv.y * mv.y + sv.y * (1.f - mv.y);
    o.z = xv.z * mv.z + sv.z * (1.f - mv.z);
    o.w = xv.w * mv.w + sv.w * (1.f - mv.w);
    reinterpret_cast<float4*>(g_vx)[idx] = o;

    o.x = xv.x * mr.x + sv.x * (1.f - mr.x);
    o.y = xv.y * mr.y + sv.y * (1.f - mr.y);
    o.z = xv.z * mr.z + sv.z * (1.f - mr.z);
    o.w = xv.w * mr.w + sv.w * (1.f - mr.w);
    reinterpret_cast<float4*>(g_rx)[idx] = o;
}

// ---------------- SGEMM: C[M,N] = A[M,K] @ B[K,N]  (+ epilogue) --------------
template <int MODE>
__global__ __launch_bounds__(256)
void sgemm_kernel(const float* __restrict__ A,
                  const float* __restrict__ B,
                  float* __restrict__ C,
                  const float* __restrict__ R) {
    constexpr int BM = 128, BN = 128, BK = 8, TM = 8, TN = 8;
    const int K = E_C, N = E_C;

    __shared__ float As[BK][BM];
    __shared__ float Bs[BK][BN];

    const int tid  = threadIdx.x;
    const int bRow = blockIdx.y;
    const int bCol = blockIdx.x;

    const int aRow = tid >> 1;
    const int aCol = (tid & 1) * 4;
    const int bR   = tid >> 5;
    const int bC   = (tid & 31) * 4;

    const int tr = tid >> 4;
    const int tc = tid & 15;

    const float* Aptr = A + (size_t)(bRow * BM) * K;
    const float* Bptr = B + bCol * BN;

    float acc[TM][TN];
    #pragma unroll
    for (int i = 0; i < TM; i++)
        #pragma unroll
        for (int j = 0; j < TN; j++) acc[i][j] = 0.f;

    for (int kt = 0; kt < K; kt += BK) {
        float4 a4 = *reinterpret_cast<const float4*>(Aptr + (size_t)aRow * K + kt + aCol);
        As[aCol + 0][aRow] = a4.x;
        As[aCol + 1][aRow] = a4.y;
        As[aCol + 2][aRow] = a4.z;
        As[aCol + 3][aRow] = a4.w;
        float4 b4 = *reinterpret_cast<const float4*>(Bptr + (size_t)(kt + bR) * N + bC);
        *reinterpret_cast<float4*>(&Bs[bR][bC]) = b4;
        __syncthreads();

        #pragma unroll
        for (int kk = 0; kk < BK; kk++) {
            float regM[TM], regN[TN];
            *reinterpret_cast<float4*>(&regM[0]) = *reinterpret_cast<const float4*>(&As[kk][tr * TM + 0]);
            *reinterpret_cast<float4*>(&regM[4]) = *reinterpret_cast<const float4*>(&As[kk][tr * TM + 4]);
            *reinterpret_cast<float4*>(&regN[0]) = *reinterpret_cast<const float4*>(&Bs[kk][tc * TN + 0]);
            *reinterpret_cast<float4*>(&regN[4]) = *reinterpret_cast<const float4*>(&Bs[kk][tc * TN + 4]);
            #pragma unroll
            for (int i = 0; i < TM; i++)
                #pragma unroll
                for (int j = 0; j < TN; j++)
                    acc[i][j] += regM[i] * regN[j];
        }
        __syncthreads();
    }

    #pragma unroll
    for (int i = 0; i < TM; i++) {
        const size_t row = (size_t)(bRow * BM + tr * TM + i);
        #pragma unroll
        for (int jj = 0; jj < TN; jj += 4) {
            const size_t idx = row * N + bCol * BN + tc * TN + jj;
            float4 v;
            v.x = acc[i][jj + 0]; v.y = acc[i][jj + 1];
            v.z = acc[i][jj + 2]; v.w = acc[i][jj + 3];
            if (MODE == 1) {
                v.x = 1.f / (1.f + __expf(-v.x));
                v.y = 1.f / (1.f + __expf(-v.y));
                v.z = 1.f / (1.f + __expf(-v.z));
                v.w = 1.f / (1.f + __expf(-v.w));
            } else if (MODE == 2) {
                float4 r4 = *reinterpret_cast<const float4*>(R + idx);
                v.x += r4.x; v.y += r4.y; v.z += r4.z; v.w += r4.w;
            }
            *reinterpret_cast<float4*>(C + idx) = v;
        }
    }
}

// ---------------- Phase A: per-segment zero-init summaries ------------------
// grid: (E/256, SEG), block 256. thread = (channel e, segment s)
__global__ __launch_bounds__(256)
void scanA_kernel(const float* __restrict__ td_in) {
    const int e = blockIdx.x * blockDim.x + threadIdx.x;
    const int s = blockIdx.y;
    const float dec = -__expf(td_in[e]);

    float aa = 0.f, bb = 0.f, pp = -1e30f;
    const size_t base = (size_t)s * SEGL * E_C + e;

    #pragma unroll 1
    for (int j = 0; j < SEGL; j += 4) {
        float kk4[4], vv4[4];
        #pragma unroll
        for (int u = 0; u < 4; u++) {
            kk4[u] = g_k[base + (size_t)(j + u) * E_C];
            vv4[u] = g_v[base + (size_t)(j + u) * E_C];
        }
        #pragma unroll
        for (int u = 0; u < 4; u++) {
            const float kk = kk4[u], vv = vv4[u];
            const float ww2 = dec + pp;
            const float d2  = ww2 - kk;
            const float m2  = __expf(-fabsf(d2));
            const float e1b = (d2 >= 0.f) ? 1.f : m2;
            const float e2b = (d2 >= 0.f) ? m2 : 1.f;
            aa = e1b * aa + e2b * vv;
            bb = e1b * bb + e2b;
            pp = (d2 >= 0.f) ? ww2 : kk;
        }
    }
    g_ua[s * E_C + e] = aa;
    g_ub[s * E_C + e] = bb;
    g_up[s * E_C + e] = pp;
}

// ---------------- Phase B: compose summaries, write per-seg initial states ---
__global__ void scanB_kernel(const float* __restrict__ aa_in,
                             const float* __restrict__ bb_in,
                             const float* __restrict__ pp_in,
                             const float* __restrict__ td_in,
                             const float* __restrict__ x,
                             float* __restrict__ out_tail,
                             int write_tail) {
    const int e = blockIdx.x * blockDim.x + threadIdx.x;
    if (e >= E_C) return;

    float aa = aa_in[e], bb = bb_in[e], pp = pp_in[e];
    const float Ld = (float)SEGL * (-__expf(td_in[e]));

    #pragma unroll 1
    for (int s = 0; s < SEG; s++) {
        g_sa[s * E_C + e] = aa;
        g_sb[s * E_C + e] = bb;
        g_sp[s * E_C + e] = pp;
        const float q  = pp + Ld;
        const float ua = g_ua[s * E_C + e];
        const float ub = g_ub[s * E_C + e];
        const float up = g_up[s * E_C + e];
        const float pn = fmaxf(q, up);
        const float eq = __expf(q - pn);
        const float eu = __expf(up - pn);
        aa = aa * eq + ua * eu;
        bb = bb * eq + ub * eu;
        pp = pn;
    }

    if (write_tail) {
        out_tail[(size_t)T_C * E_C + 0 * E_C + e] = x[(size_t)(T_C - 1) * E_C + e];
        out_tail[(size_t)T_C * E_C + 1 * E_C + e] = aa;
        out_tail[(size_t)T_C * E_C + 2 * E_C + e] = bb;
        out_tail[(size_t)T_C * E_C + 3 * E_C + e] = pp;
    }
}

// ---------------- Phase C: replay segments with true init, emit r*wkv -------
__global__ __launch_bounds__(256)
void scanC_kernel(const float* __restrict__ tf_in,
                  const float* __restrict__ td_in) {
    const int e = blockIdx.x * blockDim.x + threadIdx.x;
    const int s = blockIdx.y;
    const float tf  = tf_in[e];
    const float dec = -__expf(td_in[e]);

    float aa = g_sa[s * E_C + e];
    float bb = g_sb[s * E_C + e];
    float pp = g_sp[s * E_C + e];
    const size_t base = (size_t)s * SEGL * E_C + e;

    #pragma unroll 1
    for (int j = 0; j < SEGL; j += 4) {
        float kk4[4], vv4[4], rr4[4];
        #pragma unroll
        for (int u = 0; u < 4; u++) {
            kk4[u] = g_k[base + (size_t)(j + u) * E_C];
            vv4[u] = g_v[base + (size_t)(j + u) * E_C];
            rr4[u] = g_r[base + (size_t)(j + u) * E_C];
        }
        float out4[4];
        #pragma unroll
        for (int u = 0; u < 4; u++) {
            const float kk = kk4[u], vv = vv4[u];

            const float ww = tf + kk;
            const float d  = pp - ww;
            const float m  = __expf(-fabsf(d));
            const float e1 = (d >= 0.f) ? 1.f : m;
            const float e2 = (d >= 0.f) ? m : 1.f;
            out4[u] = rr4[u] * __fdividef(e1 * aa + e2 * vv, e1 * bb + e2);

            const float ww2 = dec + pp;
            const float d2  = ww2 - kk;
            const float m2  = __expf(-fabsf(d2));
            const float e1b = (d2 >= 0.f) ? 1.f : m2;
            const float e2b = (d2 >= 0.f) ? m2 : 1.f;
            aa = e1b * aa + e2b * vv;
            bb = e1b * bb + e2b;
            pp = (d2 >= 0.f) ? ww2 : kk;
        }
        #pragma unroll
        for (int u = 0; u < 4; u++)
            g_rwkv[base + (size_t)(j + u) * E_C] = out4[u];
    }
}

// ---------------- launch -----------------------------------------------------
extern "C" void kernel_launch(void* const* d_in, const int* in_sizes, int n_in,
                              void* d_out, int out_size) {
    const float* x   = (const float*)d_in[0];
    const float* sx  = (const float*)d_in[1];
    const float* aa  = (const float*)d_in[2];
    const float* bb  = (const float*)d_in[3];
    const float* pp  = (const float*)d_in[4];
    const float* tf  = (const float*)d_in[5];
    const float* td  = (const float*)d_in[6];
    const float* tmk = (const float*)d_in[7];
    const float* tmv = (const float*)d_in[8];
    const float* tmr = (const float*)d_in[9];
    const float* Wk  = (const float*)d_in[10];
    const float* Wv  = (const float*)d_in[11];
    const float* Wr  = (const float*)d_in[12];
    const float* Wo  = (const float*)d_in[13];
    float* out = (float*)d_out;

    float *p_kx, *p_vx, *p_rx, *p_k, *p_v, *p_r, *p_rwkv;
    cudaGetSymbolAddress((void**)&p_kx,   g_kx);
    cudaGetSymbolAddress((void**)&p_vx,   g_vx);
    cudaGetSymbolAddress((void**)&p_rx,   g_rx);
    cudaGetSymbolAddress((void**)&p_k,    g_k);
    cudaGetSymbolAddress((void**)&p_v,    g_v);
    cudaGetSymbolAddress((void**)&p_r,    g_r);
    cudaGetSymbolAddress((void**)&p_rwkv, g_rwkv);

    // 1) token-shift mixes
    {
        const int n4 = T_C * E_C / 4;
        mix_kernel<<<(n4 + 255) / 256, 256>>>(x, sx, tmk, tmv, tmr);
    }

    // 2) k, v, r GEMMs
    dim3 ggrid(E_C / 128, T_C / 128);
    sgemm_kernel<0><<<ggrid, 256>>>(p_kx, Wk, p_k, nullptr);
    sgemm_kernel<0><<<ggrid, 256>>>(p_vx, Wv, p_v, nullptr);
    sgemm_kernel<1><<<ggrid, 256>>>(p_rx, Wr, p_r, nullptr);

    // 3) segment-parallel WKV scan
    const int write_tail = (out_size >= T_C * E_C + 4 * E_C) ? 1 : 0;
    dim3 sgrid(E_C / 256, SEG);
    scanA_kernel<<<sgrid, 256>>>(td);
    scanB_kernel<<<4, 256>>>(aa, bb, pp, td, x, out, write_tail);
    scanC_kernel<<<sgrid, 256>>>(tf, td);

    // 4) out = x + rwkv @ Wo
    sgemm_kernel<2><<<ggrid, 256>>>(p_rwkv, Wo, out, x);
}

// round 6
// speedup vs baseline: 5.6491x; 3.4547x over previous
#include <cuda_runtime.h>
#include <math.h>
#include <stdint.h>

#define T_C 8192
#define E_C 1024
#define SEG 64
#define SEGL (T_C / SEG)   // 128

// ---------------- scratch (device globals; no allocations allowed) ----------
__device__ float g_kx[T_C * E_C];
__device__ float g_vx[T_C * E_C];
__device__ float g_rx[T_C * E_C];
__device__ float g_k [T_C * E_C];
__device__ float g_v [T_C * E_C];
__device__ float g_r [T_C * E_C];
__device__ float g_rwkv[T_C * E_C];
__device__ float g_bt[4 * E_C * E_C];   // transposed weights [N,K] K-major (tf32-rounded)
// segment summaries / initial states
__device__ float g_ua[SEG * E_C];
__device__ float g_ub[SEG * E_C];
__device__ float g_up[SEG * E_C];
__device__ float g_sa[SEG * E_C];
__device__ float g_sb[SEG * E_C];
__device__ float g_sp[SEG * E_C];

// ---------------- PTX helpers (compute_103-portable only) --------------------
__device__ __forceinline__ float tf32r(float x) {
    float y;
    asm("cvt.rna.tf32.f32 %0, %1;" : "=f"(y) : "f"(x));
    return y;
}

__device__ __forceinline__ uint32_t smem_u32(const void* p) {
    uint32_t a;
    asm("{ .reg .u64 t; cvta.to.shared.u64 t, %1; cvt.u32.u64 %0, t; }"
        : "=r"(a) : "l"(p));
    return a;
}

__device__ __forceinline__ void cp16(uint32_t dst, const void* src) {
    asm volatile("cp.async.cg.shared.global [%0], [%1], 16;" :: "r"(dst), "l"(src));
}

__device__ __forceinline__ void ldsm4(uint32_t* r, uint32_t addr) {
    asm volatile("ldmatrix.sync.aligned.m8n8.x4.shared.b16 {%0,%1,%2,%3}, [%4];"
                 : "=r"(r[0]), "=r"(r[1]), "=r"(r[2]), "=r"(r[3]) : "r"(addr));
}

__device__ __forceinline__ void mma_tf32(float* c, const uint32_t* a,
                                         uint32_t b0, uint32_t b1) {
    asm volatile(
        "mma.sync.aligned.m16n8k8.row.col.f32.tf32.tf32.f32 "
        "{%0,%1,%2,%3},{%4,%5,%6,%7},{%8,%9},{%0,%1,%2,%3};"
        : "+f"(c[0]), "+f"(c[1]), "+f"(c[2]), "+f"(c[3])
        : "r"(a[0]), "r"(a[1]), "r"(a[2]), "r"(a[3]), "r"(b0), "r"(b1));
}

#define SWZ(off) ((off) ^ (((off) >> 3) & 0x70))

// ---------------- token-shift mix (tf32-rounded outputs) ---------------------
__global__ void mix_kernel(const float* __restrict__ x,
                           const float* __restrict__ sx,
                           const float* __restrict__ tmk,
                           const float* __restrict__ tmv,
                           const float* __restrict__ tmr) {
    int idx = blockIdx.x * blockDim.x + threadIdx.x;
    const int n4 = T_C * E_C / 4;
    if (idx >= n4) return;
    const int E4 = E_C / 4;
    int e4 = idx % E4;
    int t  = idx / E4;

    float4 xv = reinterpret_cast<const float4*>(x)[idx];
    float4 sv = (t == 0) ? reinterpret_cast<const float4*>(sx)[e4]
                         : reinterpret_cast<const float4*>(x)[idx - E4];
    float4 mk = reinterpret_cast<const float4*>(tmk)[e4];
    float4 mv = reinterpret_cast<const float4*>(tmv)[e4];
    float4 mr = reinterpret_cast<const float4*>(tmr)[e4];

    float4 o;
    o.x = tf32r(xv.x * mk.x + sv.x * (1.f - mk.x));
    o.y = tf32r(xv.y * mk.y + sv.y * (1.f - mk.y));
    o.z = tf32r(xv.z * mk.z + sv.z * (1.f - mk.z));
    o.w = tf32r(xv.w * mk.w + sv.w * (1.f - mk.w));
    reinterpret_cast<float4*>(g_kx)[idx] = o;

    o.x = tf32r(xv.x * mv.x + sv.x * (1.f - mv.x));
    o.y = tf32r(xv.y * mv.y + sv.y * (1.f - mv.y));
    o.z = tf32r(xv.z * mv.z + sv.z * (1.f - mv.z));
    o.w = tf32r(xv.w * mv.w + sv.w * (1.f - mv.w));
    reinterpret_cast<float4*>(g_vx)[idx] = o;

    o.x = tf32r(xv.x * mr.x + sv.x * (1.f - mr.x));
    o.y = tf32r(xv.y * mr.y + sv.y * (1.f - mr.y));
    o.z = tf32r(xv.z * mr.z + sv.z * (1.f - mr.z));
    o.w = tf32r(xv.w * mr.w + sv.w * (1.f - mr.w));
    reinterpret_cast<float4*>(g_rx)[idx] = o;
}

// ---------------- weight transpose: g_bt[z][n][k] = rna(W_z[k][n]) -----------
__global__ void transpose_kernel(const float* __restrict__ Wk,
                                 const float* __restrict__ Wv,
                                 const float* __restrict__ Wr,
                                 const float* __restrict__ Wo) {
    __shared__ float t[32][33];
    const float* src = (blockIdx.z == 0) ? Wk : (blockIdx.z == 1) ? Wv
                     : (blockIdx.z == 2) ? Wr : Wo;
    float* dst = g_bt + (size_t)blockIdx.z * (E_C * E_C);

    int x  = blockIdx.x * 32 + threadIdx.x;
    int y0 = blockIdx.y * 32;
    #pragma unroll
    for (int j = threadIdx.y; j < 32; j += 8)
        t[j][threadIdx.x] = src[(size_t)(y0 + j) * E_C + x];
    __syncthreads();
    int xo  = blockIdx.y * 32 + threadIdx.x;
    int yo0 = blockIdx.x * 32;
    #pragma unroll
    for (int j = threadIdx.y; j < 32; j += 8)
        dst[(size_t)(yo0 + j) * E_C + xo] = tf32r(t[threadIdx.x][j]);
}

// ---------------- tf32 HMMA GEMM --------------------------------------------
// C[8192,1024] = A[8192,1024] @ Bt[1024,1024]^T   (Bt is [N,K] K-major)
// MODE 0: plain, MODE 1: sigmoid, MODE 2: C = R + acc
#define GSTAGES 4
#define GNITER  32          // K / 32
#define GSMEM_BYTES (GSTAGES * 32768)

__device__ __forceinline__ void gemm_load_stage(const float* Abase, const float* Bbase,
                                                uint32_t stA, int k0, int tid) {
    #pragma unroll
    for (int i = 0; i < 4; i++) {
        int u = i * 256 + tid;
        int row = u >> 3, c = u & 7;
        uint32_t off = (uint32_t)(row * 128 + c * 16);
        cp16(stA + SWZ(off), Abase + (size_t)row * E_C + k0 + c * 4);
    }
    uint32_t stB = stA + 16384u;
    #pragma unroll
    for (int i = 0; i < 4; i++) {
        int u = i * 256 + tid;
        int row = u >> 3, c = u & 7;
        uint32_t off = (uint32_t)(row * 128 + c * 16);
        cp16(stB + SWZ(off), Bbase + (size_t)row * E_C + k0 + c * 4);
    }
    asm volatile("cp.async.commit_group;" ::: "memory");
}

template <int MODE>
__global__ __launch_bounds__(256)
void mma_gemm_kernel(const float* __restrict__ A,
                     const float* __restrict__ Bt,
                     float* __restrict__ C,
                     const float* __restrict__ R) {
    extern __shared__ char smem[];
    const uint32_t TILES = smem_u32(smem);
    const int tid = threadIdx.x;
    const int wid = tid >> 5;
    const int lid = tid & 31;
    const int bN = blockIdx.x, bM = blockIdx.y;

    // warp tile: 64 (m) x 32 (n); warps arranged 2 x 4
    const int warp_m = (wid >> 2) * 64;
    const int warp_n = (wid & 3) * 32;

    const int lrow = lid & 7;
    const int g    = lid >> 3;           // ldmatrix tile group 0..3

    const float* Abase = A  + (size_t)bM * 128 * E_C;
    const float* Bbase = Bt + (size_t)bN * 128 * E_C;

    float acc[4][4][4];                  // [mb][nb][reg]
    #pragma unroll
    for (int mb = 0; mb < 4; mb++)
        #pragma unroll
        for (int nb = 0; nb < 4; nb++)
            #pragma unroll
            for (int q = 0; q < 4; q++) acc[mb][nb][q] = 0.f;

    // prologue: 3 stages in flight
    #pragma unroll
    for (int s = 0; s < GSTAGES - 1; s++)
        gemm_load_stage(Abase, Bbase, TILES + (uint32_t)s * 32768u, s * 32, tid);

    for (int kt = 0; kt < GNITER; kt++) {
        if (kt >= GNITER - 1)
            asm volatile("cp.async.wait_group 0;" ::: "memory");
        else if (kt >= GNITER - 2)
            asm volatile("cp.async.wait_group 1;" ::: "memory");
        else
            asm volatile("cp.async.wait_group 2;" ::: "memory");
        __syncthreads();

        const uint32_t sA = TILES + (uint32_t)(kt & (GSTAGES - 1)) * 32768u;
        const uint32_t sB = sA + 16384u;

        #pragma unroll
        for (int ks = 0; ks < 4; ks++) {
            uint32_t af[4][4];
            #pragma unroll
            for (int mb = 0; mb < 4; mb++) {
                int row   = warp_m + mb * 16 + lrow + (g & 1) * 8;
                int chunk = ks * 2 + (g >> 1);
                ldsm4(af[mb], sA + SWZ((uint32_t)(row * 128 + chunk * 16)));
            }
            uint32_t bf[2][4];
            #pragma unroll
            for (int nb2 = 0; nb2 < 2; nb2++) {
                int nrow  = warp_n + nb2 * 16 + lrow + (g >> 1) * 8;
                int chunk = ks * 2 + (g & 1);
                ldsm4(bf[nb2], sB + SWZ((uint32_t)(nrow * 128 + chunk * 16)));
            }
            #pragma unroll
            for (int mb = 0; mb < 4; mb++)
                #pragma unroll
                for (int nb = 0; nb < 4; nb++)
                    mma_tf32(acc[mb][nb], af[mb],
                             bf[nb >> 1][(nb & 1) * 2], bf[nb >> 1][(nb & 1) * 2 + 1]);
        }

        if (kt + GSTAGES - 1 < GNITER)
            gemm_load_stage(Abase, Bbase,
                            TILES + (uint32_t)((kt + GSTAGES - 1) & (GSTAGES - 1)) * 32768u,
                            (kt + GSTAGES - 1) * 32, tid);
    }

    // epilogue: direct register -> global stores
    #pragma unroll
    for (int mb = 0; mb < 4; mb++) {
        #pragma unroll
        for (int nb = 0; nb < 4; nb++) {
            const int row0 = bM * 128 + warp_m + mb * 16 + (lid >> 2);
            const int col  = bN * 128 + warp_n + nb * 8 + 2 * (lid & 3);
            #pragma unroll
            for (int h = 0; h < 2; h++) {
                float2 v;
                v.x = acc[mb][nb][h * 2 + 0];
                v.y = acc[mb][nb][h * 2 + 1];
                const size_t idx = (size_t)(row0 + h * 8) * E_C + col;
                if (MODE == 1) {
                    v.x = 1.f / (1.f + __expf(-v.x));
                    v.y = 1.f / (1.f + __expf(-v.y));
                } else if (MODE == 2) {
                    float2 r2 = *reinterpret_cast<const float2*>(R + idx);
                    v.x += r2.x; v.y += r2.y;
                }
                *reinterpret_cast<float2*>(C + idx) = v;
            }
        }
    }
}

// ---------------- Phase A: per-segment zero-init summaries ------------------
__global__ __launch_bounds__(256)
void scanA_kernel(const float* __restrict__ td_in) {
    const int e = blockIdx.x * blockDim.x + threadIdx.x;
    const int s = blockIdx.y;
    const float dec = -__expf(td_in[e]);

    float aa = 0.f, bb = 0.f, pp = -1e30f;
    const size_t base = (size_t)s * SEGL * E_C + e;

    #pragma unroll 1
    for (int j = 0; j < SEGL; j += 4) {
        float kk4[4], vv4[4];
        #pragma unroll
        for (int u = 0; u < 4; u++) {
            kk4[u] = g_k[base + (size_t)(j + u) * E_C];
            vv4[u] = g_v[base + (size_t)(j + u) * E_C];
        }
        #pragma unroll
        for (int u = 0; u < 4; u++) {
            const float kk = kk4[u], vv = vv4[u];
            const float ww2 = dec + pp;
            const float d2  = ww2 - kk;
            const float m2  = __expf(-fabsf(d2));
            const float e1b = (d2 >= 0.f) ? 1.f : m2;
            const float e2b = (d2 >= 0.f) ? m2 : 1.f;
            aa = e1b * aa + e2b * vv;
            bb = e1b * bb + e2b;
            pp = (d2 >= 0.f) ? ww2 : kk;
        }
    }
    g_ua[s * E_C + e] = aa;
    g_ub[s * E_C + e] = bb;
    g_up[s * E_C + e] = pp;
}

// ---------------- Phase B: compose summaries --------------------------------
__global__ void scanB_kernel(const float* __restrict__ aa_in,
                             const float* __restrict__ bb_in,
                             const float* __restrict__ pp_in,
                             const float* __restrict__ td_in,
                             const float* __restrict__ x,
                             float* __restrict__ out_tail,
                             int write_tail) {
    const int e = blockIdx.x * blockDim.x + threadIdx.x;
    if (e >= E_C) return;

    float aa = aa_in[e], bb = bb_in[e], pp = pp_in[e];
    const float Ld = (float)SEGL * (-__expf(td_in[e]));

    #pragma unroll 1
    for (int s = 0; s < SEG; s++) {
        g_sa[s * E_C + e] = aa;
        g_sb[s * E_C + e] = bb;
        g_sp[s * E_C + e] = pp;
        const float q  = pp + Ld;
        const float ua = g_ua[s * E_C + e];
        const float ub = g_ub[s * E_C + e];
        const float up = g_up[s * E_C + e];
        const float pn = fmaxf(q, up);
        const float eq = __expf(q - pn);
        const float eu = __expf(up - pn);
        aa = aa * eq + ua * eu;
        bb = bb * eq + ub * eu;
        pp = pn;
    }

    if (write_tail) {
        out_tail[(size_t)T_C * E_C + 0 * E_C + e] = x[(size_t)(T_C - 1) * E_C + e];
        out_tail[(size_t)T_C * E_C + 1 * E_C + e] = aa;
        out_tail[(size_t)T_C * E_C + 2 * E_C + e] = bb;
        out_tail[(size_t)T_C * E_C + 3 * E_C + e] = pp;
    }
}

// ---------------- Phase C: replay segments, emit tf32-rounded r*wkv ---------
__global__ __launch_bounds__(256)
void scanC_kernel(const float* __restrict__ tf_in,
                  const float* __restrict__ td_in) {
    const int e = blockIdx.x * blockDim.x + threadIdx.x;
    const int s = blockIdx.y;
    const float tf  = tf_in[e];
    const float dec = -__expf(td_in[e]);

    float aa = g_sa[s * E_C + e];
    float bb = g_sb[s * E_C + e];
    float pp = g_sp[s * E_C + e];
    const size_t base = (size_t)s * SEGL * E_C + e;

    #pragma unroll 1
    for (int j = 0; j < SEGL; j += 4) {
        float kk4[4], vv4[4], rr4[4];
        #pragma unroll
        for (int u = 0; u < 4; u++) {
            kk4[u] = g_k[base + (size_t)(j + u) * E_C];
            vv4[u] = g_v[base + (size_t)(j + u) * E_C];
            rr4[u] = g_r[base + (size_t)(j + u) * E_C];
        }
        float out4[4];
        #pragma unroll
        for (int u = 0; u < 4; u++) {
            const float kk = kk4[u], vv = vv4[u];

            const float ww = tf + kk;
            const float d  = pp - ww;
            const float m  = __expf(-fabsf(d));
            const float e1 = (d >= 0.f) ? 1.f : m;
            const float e2 = (d >= 0.f) ? m : 1.f;
            out4[u] = tf32r(rr4[u] * __fdividef(e1 * aa + e2 * vv, e1 * bb + e2));

            const float ww2 = dec + pp;
            const float d2  = ww2 - kk;
            const float m2  = __expf(-fabsf(d2));
            const float e1b = (d2 >= 0.f) ? 1.f : m2;
            const float e2b = (d2 >= 0.f) ? m2 : 1.f;
            aa = e1b * aa + e2b * vv;
            bb = e1b * bb + e2b;
            pp = (d2 >= 0.f) ? ww2 : kk;
        }
        #pragma unroll
        for (int u = 0; u < 4; u++)
            g_rwkv[base + (size_t)(j + u) * E_C] = out4[u];
    }
}

// ---------------- launch -----------------------------------------------------
extern "C" void kernel_launch(void* const* d_in, const int* in_sizes, int n_in,
                              void* d_out, int out_size) {
    const float* x   = (const float*)d_in[0];
    const float* sx  = (const float*)d_in[1];
    const float* aa  = (const float*)d_in[2];
    const float* bb  = (const float*)d_in[3];
    const float* pp  = (const float*)d_in[4];
    const float* tf  = (const float*)d_in[5];
    const float* td  = (const float*)d_in[6];
    const float* tmk = (const float*)d_in[7];
    const float* tmv = (const float*)d_in[8];
    const float* tmr = (const float*)d_in[9];
    const float* Wk  = (const float*)d_in[10];
    const float* Wv  = (const float*)d_in[11];
    const float* Wr  = (const float*)d_in[12];
    const float* Wo  = (const float*)d_in[13];
    float* out = (float*)d_out;

    float *p_kx, *p_vx, *p_rx, *p_k, *p_v, *p_r, *p_rwkv, *p_bt;
    cudaGetSymbolAddress((void**)&p_kx,   g_kx);
    cudaGetSymbolAddress((void**)&p_vx,   g_vx);
    cudaGetSymbolAddress((void**)&p_rx,   g_rx);
    cudaGetSymbolAddress((void**)&p_k,    g_k);
    cudaGetSymbolAddress((void**)&p_v,    g_v);
    cudaGetSymbolAddress((void**)&p_r,    g_r);
    cudaGetSymbolAddress((void**)&p_rwkv, g_rwkv);
    cudaGetSymbolAddress((void**)&p_bt,   g_bt);

    cudaFuncSetAttribute(mma_gemm_kernel<0>,
                         cudaFuncAttributeMaxDynamicSharedMemorySize, GSMEM_BYTES);
    cudaFuncSetAttribute(mma_gemm_kernel<1>,
                         cudaFuncAttributeMaxDynamicSharedMemorySize, GSMEM_BYTES);
    cudaFuncSetAttribute(mma_gemm_kernel<2>,
                         cudaFuncAttributeMaxDynamicSharedMemorySize, GSMEM_BYTES);

    // 1) token-shift mixes (tf32-rounded)
    {
        const int n4 = T_C * E_C / 4;
        mix_kernel<<<(n4 + 255) / 256, 256>>>(x, sx, tmk, tmv, tmr);
    }

    // 2) weight transposes -> [N,K] K-major, tf32-rounded
    transpose_kernel<<<dim3(32, 32, 4), dim3(32, 8)>>>(Wk, Wv, Wr, Wo);

    // 3) k, v, r GEMMs on tensor cores (HMMA tf32)
    dim3 ggrid(E_C / 128, T_C / 128);
    mma_gemm_kernel<0><<<ggrid, 256, GSMEM_BYTES>>>(p_kx, p_bt + 0 * (size_t)E_C * E_C, p_k, nullptr);
    mma_gemm_kernel<0><<<ggrid, 256, GSMEM_BYTES>>>(p_vx, p_bt + 1 * (size_t)E_C * E_C, p_v, nullptr);
    mma_gemm_kernel<1><<<ggrid, 256, GSMEM_BYTES>>>(p_rx, p_bt + 2 * (size_t)E_C * E_C, p_r, nullptr);

    // 4) segment-parallel WKV scan
    const int write_tail = (out_size >= T_C * E_C + 4 * E_C) ? 1 : 0;
    dim3 sgrid(E_C / 256, SEG);
    scanA_kernel<<<sgrid, 256>>>(td);
    scanB_kernel<<<4, 256>>>(aa, bb, pp, td, x, out, write_tail);
    scanC_kernel<<<sgrid, 256>>>(tf, td);

    // 5) out = x + rwkv @ Wo
    mma_gemm_kernel<2><<<ggrid, 256, GSMEM_BYTES>>>(p_rwkv, p_bt + 3 * (size_t)E_C * E_C, out, x);
}

// round 9
// speedup vs baseline: 6.7704x; 1.1985x over previous
#include <cuda_runtime.h>
#include <math.h>
#include <stdint.h>

#define T_C 8192
#define E_C 1024
#define SEG 64
#define SEGL (T_C / SEG)   // 128

// ---------------- scratch (device globals; no allocations allowed) ----------
__device__ float g_mix[3][T_C * E_C];   // kx, vx, rx
__device__ float g_kvr[3][T_C * E_C];   // k, v, r
__device__ float g_rwkv[T_C * E_C];
__device__ float g_bt[4 * E_C * E_C];   // transposed weights [N,K] K-major (tf32-rounded)
// segment summaries / initial states
__device__ float g_ua[SEG * E_C];
__device__ float g_ub[SEG * E_C];
__device__ float g_up[SEG * E_C];
__device__ float g_sa[SEG * E_C];
__device__ float g_sb[SEG * E_C];
__device__ float g_sp[SEG * E_C];

// ---------------- PTX helpers (compute_103-portable only) --------------------
__device__ __forceinline__ float tf32r(float x) {
    float y;
    asm("cvt.rna.tf32.f32 %0, %1;" : "=f"(y) : "f"(x));
    return y;
}

__device__ __forceinline__ uint32_t smem_u32(const void* p) {
    uint32_t a;
    asm("{ .reg .u64 t; cvta.to.shared.u64 t, %1; cvt.u32.u64 %0, t; }"
        : "=r"(a) : "l"(p));
    return a;
}

__device__ __forceinline__ void cp16(uint32_t dst, const void* src) {
    asm volatile("cp.async.cg.shared.global [%0], [%1], 16;" :: "r"(dst), "l"(src));
}

__device__ __forceinline__ void ldsm4(uint32_t* r, uint32_t addr) {
    asm volatile("ldmatrix.sync.aligned.m8n8.x4.shared.b16 {%0,%1,%2,%3}, [%4];"
                 : "=r"(r[0]), "=r"(r[1]), "=r"(r[2]), "=r"(r[3]) : "r"(addr));
}

__device__ __forceinline__ void mma_tf32(float* c, const uint32_t* a,
                                         uint32_t b0, uint32_t b1) {
    asm volatile(
        "mma.sync.aligned.m16n8k8.row.col.f32.tf32.tf32.f32 "
        "{%0,%1,%2,%3},{%4,%5,%6,%7},{%8,%9},{%0,%1,%2,%3};"
        : "+f"(c[0]), "+f"(c[1]), "+f"(c[2]), "+f"(c[3])
        : "r"(a[0]), "r"(a[1]), "r"(a[2]), "r"(a[3]), "r"(b0), "r"(b1));
}

#define SWZ(off) ((off) ^ (((off) >> 3) & 0x70))

// ---------------- token-shift mix (tf32-rounded outputs) ---------------------
__global__ void mix_kernel(const float* __restrict__ x,
                           const float* __restrict__ sx,
                           const float* __restrict__ tmk,
                           const float* __restrict__ tmv,
                           const float* __restrict__ tmr) {
    int idx = blockIdx.x * blockDim.x + threadIdx.x;
    const int n4 = T_C * E_C / 4;
    if (idx >= n4) return;
    const int E4 = E_C / 4;
    int e4 = idx % E4;
    int t  = idx / E4;

    float4 xv = reinterpret_cast<const float4*>(x)[idx];
    float4 sv = (t == 0) ? reinterpret_cast<const float4*>(sx)[e4]
                         : reinterpret_cast<const float4*>(x)[idx - E4];
    float4 mk = reinterpret_cast<const float4*>(tmk)[e4];
    float4 mv = reinterpret_cast<const float4*>(tmv)[e4];
    float4 mr = reinterpret_cast<const float4*>(tmr)[e4];

    float4 o;
    o.x = tf32r(xv.x * mk.x + sv.x * (1.f - mk.x));
    o.y = tf32r(xv.y * mk.y + sv.y * (1.f - mk.y));
    o.z = tf32r(xv.z * mk.z + sv.z * (1.f - mk.z));
    o.w = tf32r(xv.w * mk.w + sv.w * (1.f - mk.w));
    reinterpret_cast<float4*>(g_mix[0])[idx] = o;

    o.x = tf32r(xv.x * mv.x + sv.x * (1.f - mv.x));
    o.y = tf32r(xv.y * mv.y + sv.y * (1.f - mv.y));
    o.z = tf32r(xv.z * mv.z + sv.z * (1.f - mv.z));
    o.w = tf32r(xv.w * mv.w + sv.w * (1.f - mv.w));
    reinterpret_cast<float4*>(g_mix[1])[idx] = o;

    o.x = tf32r(xv.x * mr.x + sv.x * (1.f - mr.x));
    o.y = tf32r(xv.y * mr.y + sv.y * (1.f - mr.y));
    o.z = tf32r(xv.z * mr.z + sv.z * (1.f - mr.z));
    o.w = tf32r(xv.w * mr.w + sv.w * (1.f - mr.w));
    reinterpret_cast<float4*>(g_mix[2])[idx] = o;
}

// ---------------- weight transpose: g_bt[z][n][k] = rna(W_z[k][n]) -----------
__global__ void transpose_kernel(const float* __restrict__ Wk,
                                 const float* __restrict__ Wv,
                                 const float* __restrict__ Wr,
                                 const float* __restrict__ Wo) {
    __shared__ float t[32][33];
    const float* src = (blockIdx.z == 0) ? Wk : (blockIdx.z == 1) ? Wv
                     : (blockIdx.z == 2) ? Wr : Wo;
    float* dst = g_bt + (size_t)blockIdx.z * (E_C * E_C);

    int x  = blockIdx.x * 32 + threadIdx.x;
    int y0 = blockIdx.y * 32;
    #pragma unroll
    for (int j = threadIdx.y; j < 32; j += 8)
        t[j][threadIdx.x] = src[(size_t)(y0 + j) * E_C + x];
    __syncthreads();
    int xo  = blockIdx.y * 32 + threadIdx.x;
    int yo0 = blockIdx.x * 32;
    #pragma unroll
    for (int j = threadIdx.y; j < 32; j += 8)
        dst[(size_t)(yo0 + j) * E_C + xo] = tf32r(t[threadIdx.x][j]);
}

// ---------------- tf32 HMMA GEMM core ----------------------------------------
// 3-stage cp.async pipeline, 128x128 CTA tile, 2 CTAs/SM.
#define GSTAGES 3
#define GNITER  32          // K / 32
#define GSMEM_BYTES (GSTAGES * 32768)

__device__ __forceinline__ void gemm_load_stage(const float* Abase, const float* Bbase,
                                                uint32_t stA, int k0, int tid) {
    #pragma unroll
    for (int i = 0; i < 4; i++) {
        int u = i * 256 + tid;
        int row = u >> 3, c = u & 7;
        uint32_t off = (uint32_t)(row * 128 + c * 16);
        cp16(stA + SWZ(off), Abase + (size_t)row * E_C + k0 + c * 4);
    }
    uint32_t stB = stA + 16384u;
    #pragma unroll
    for (int i = 0; i < 4; i++) {
        int u = i * 256 + tid;
        int row = u >> 3, c = u & 7;
        uint32_t off = (uint32_t)(row * 128 + c * 16);
        cp16(stB + SWZ(off), Bbase + (size_t)row * E_C + k0 + c * 4);
    }
    asm volatile("cp.async.commit_group;" ::: "memory");
}

// body shared by both GEMM kernels; mode: 0 plain, 1 sigmoid, 2 residual
__device__ __forceinline__ void gemm_body(const float* __restrict__ A,
                                          const float* __restrict__ Bt,
                                          float* __restrict__ C,
                                          const float* __restrict__ R,
                                          int mode, int bN, int bM) {
    extern __shared__ char smem[];
    const uint32_t TILES = smem_u32(smem);
    const int tid = threadIdx.x;
    const int wid = tid >> 5;
    const int lid = tid & 31;

    const int warp_m = (wid >> 2) * 64;
    const int warp_n = (wid & 3) * 32;

    const int lrow = lid & 7;
    const int g    = lid >> 3;

    const float* Abase = A  + (size_t)bM * 128 * E_C;
    const float* Bbase = Bt + (size_t)bN * 128 * E_C;

    float acc[4][4][4];
    #pragma unroll
    for (int mb = 0; mb < 4; mb++)
        #pragma unroll
        for (int nb = 0; nb < 4; nb++)
            #pragma unroll
            for (int q = 0; q < 4; q++) acc[mb][nb][q] = 0.f;

    // prologue: 2 stages in flight
    #pragma unroll
    for (int s = 0; s < GSTAGES - 1; s++)
        gemm_load_stage(Abase, Bbase, TILES + (uint32_t)s * 32768u, s * 32, tid);

    for (int kt = 0; kt < GNITER; kt++) {
        if (kt >= GNITER - 1)
            asm volatile("cp.async.wait_group 0;" ::: "memory");
        else
            asm volatile("cp.async.wait_group 1;" ::: "memory");
        __syncthreads();

        const uint32_t sA = TILES + (uint32_t)(kt % GSTAGES) * 32768u;
        const uint32_t sB = sA + 16384u;

        #pragma unroll
        for (int ks = 0; ks < 4; ks++) {
            uint32_t af[4][4];
            #pragma unroll
            for (int mb = 0; mb < 4; mb++) {
                int row   = warp_m + mb * 16 + lrow + (g & 1) * 8;
                int chunk = ks * 2 + (g >> 1);
                ldsm4(af[mb], sA + SWZ((uint32_t)(row * 128 + chunk * 16)));
            }
            uint32_t bf[2][4];
            #pragma unroll
            for (int nb2 = 0; nb2 < 2; nb2++) {
                int nrow  = warp_n + nb2 * 16 + lrow + (g >> 1) * 8;
                int chunk = ks * 2 + (g & 1);
                ldsm4(bf[nb2], sB + SWZ((uint32_t)(nrow * 128 + chunk * 16)));
            }
            #pragma unroll
            for (int mb = 0; mb < 4; mb++)
                #pragma unroll
                for (int nb = 0; nb < 4; nb++)
                    mma_tf32(acc[mb][nb], af[mb],
                             bf[nb >> 1][(nb & 1) * 2], bf[nb >> 1][(nb & 1) * 2 + 1]);
        }

        if (kt + GSTAGES - 1 < GNITER) {
            __syncthreads();
            gemm_load_stage(Abase, Bbase,
                            TILES + (uint32_t)((kt + GSTAGES - 1) % GSTAGES) * 32768u,
                            (kt + GSTAGES - 1) * 32, tid);
        }
    }

    #pragma unroll
    for (int mb = 0; mb < 4; mb++) {
        #pragma unroll
        for (int nb = 0; nb < 4; nb++) {
            const int row0 = bM * 128 + warp_m + mb * 16 + (lid >> 2);
            const int col  = bN * 128 + warp_n + nb * 8 + 2 * (lid & 3);
            #pragma unroll
            for (int h = 0; h < 2; h++) {
                float2 v;
                v.x = acc[mb][nb][h * 2 + 0];
                v.y = acc[mb][nb][h * 2 + 1];
                const size_t idx = (size_t)(row0 + h * 8) * E_C + col;
                if (mode == 1) {
                    v.x = 1.f / (1.f + __expf(-v.x));
                    v.y = 1.f / (1.f + __expf(-v.y));
                } else if (mode == 2) {
                    float2 r2 = *reinterpret_cast<const float2*>(R + idx);
                    v.x += r2.x; v.y += r2.y;
                }
                *reinterpret_cast<float2*>(C + idx) = v;
            }
        }
    }
}

// merged k/v/r GEMM: blockIdx.z selects slice; z==2 applies sigmoid
__global__ __launch_bounds__(256, 2)
void gemm_kvr_kernel() {
    const int z = blockIdx.z;
    gemm_body(g_mix[z], g_bt + (size_t)z * E_C * E_C, g_kvr[z], nullptr,
              (z == 2) ? 1 : 0, blockIdx.x, blockIdx.y);
}

// final GEMM: out = x + rwkv @ Wo
__global__ __launch_bounds__(256, 2)
void gemm_out_kernel(float* __restrict__ C, const float* __restrict__ R) {
    gemm_body(g_rwkv, g_bt + 3 * (size_t)E_C * E_C, C, R, 2, blockIdx.x, blockIdx.y);
}

// ---------------- Phase A: per-segment zero-init summaries ------------------
__global__ __launch_bounds__(256)
void scanA_kernel(const float* __restrict__ td_in) {
    const int e = blockIdx.x * blockDim.x + threadIdx.x;
    const int s = blockIdx.y;
    const float dec = -__expf(td_in[e]);

    float aa = 0.f, bb = 0.f, pp = -1e30f;
    const size_t base = (size_t)s * SEGL * E_C + e;

    #pragma unroll 1
    for (int j = 0; j < SEGL; j += 4) {
        float kk4[4], vv4[4];
        #pragma unroll
        for (int u = 0; u < 4; u++) {
            kk4[u] = g_kvr[0][base + (size_t)(j + u) * E_C];
            vv4[u] = g_kvr[1][base + (size_t)(j + u) * E_C];
        }
        #pragma unroll
        for (int u = 0; u < 4; u++) {
            const float kk = kk4[u], vv = vv4[u];
            const float ww2 = dec + pp;
            const float d2  = ww2 - kk;
            const float m2  = __expf(-fabsf(d2));
            const float e1b = (d2 >= 0.f) ? 1.f : m2;
            const float e2b = (d2 >= 0.f) ? m2 : 1.f;
            aa = e1b * aa + e2b * vv;
            bb = e1b * bb + e2b;
            pp = (d2 >= 0.f) ? ww2 : kk;
        }
    }
    g_ua[s * E_C + e] = aa;
    g_ub[s * E_C + e] = bb;
    g_up[s * E_C + e] = pp;
}

// ---------------- Phase B: compose summaries --------------------------------
__global__ void scanB_kernel(const float* __restrict__ aa_in,
                             const float* __restrict__ bb_in,
                             const float* __restrict__ pp_in,
                             const float* __restrict__ td_in,
                             const float* __restrict__ x,
                             float* __restrict__ out_tail,
                             int write_tail) {
    const int e = blockIdx.x * blockDim.x + threadIdx.x;
    if (e >= E_C) return;

    float aa = aa_in[e], bb = bb_in[e], pp = pp_in[e];
    const float Ld = (float)SEGL * (-__expf(td_in[e]));

    #pragma unroll 1
    for (int s = 0; s < SEG; s++) {
        g_sa[s * E_C + e] = aa;
        g_sb[s * E_C + e] = bb;
        g_sp[s * E_C + e] = pp;
        const float q  = pp + Ld;
        const float ua = g_ua[s * E_C + e];
        const float ub = g_ub[s * E_C + e];
        const float up = g_up[s * E_C + e];
        const float pn = fmaxf(q, up);
        const float eq = __expf(q - pn);
        const float eu = __expf(up - pn);
        aa = aa * eq + ua * eu;
        bb = bb * eq + ub * eu;
        pp = pn;
    }

    if (write_tail) {
        out_tail[(size_t)T_C * E_C + 0 * E_C + e] = x[(size_t)(T_C - 1) * E_C + e];
        out_tail[(size_t)T_C * E_C + 1 * E_C + e] = aa;
        out_tail[(size_t)T_C * E_C + 2 * E_C + e] = bb;
        out_tail[(size_t)T_C * E_C + 3 * E_C + e] = pp;
    }
}

// ---------------- Phase C: replay segments, emit tf32-rounded r*wkv ---------
__global__ __launch_bounds__(256)
void scanC_kernel(const float* __restrict__ tf_in,
                  const float* __restrict__ td_in) {
    const int e = blockIdx.x * blockDim.x + threadIdx.x;
    const int s = blockIdx.y;
    const float tf  = tf_in[e];
    const float dec = -__expf(td_in[e]);

    float aa = g_sa[s * E_C + e];
    float bb = g_sb[s * E_C + e];
    float pp = g_sp[s * E_C + e];
    const size_t base = (size_t)s * SEGL * E_C + e;

    #pragma unroll 1
    for (int j = 0; j < SEGL; j += 4) {
        float kk4[4], vv4[4], rr4[4];
        #pragma unroll
        for (int u = 0; u < 4; u++) {
            kk4[u] = g_kvr[0][base + (size_t)(j + u) * E_C];
            vv4[u] = g_kvr[1][base + (size_t)(j + u) * E_C];
            rr4[u] = g_kvr[2][base + (size_t)(j + u) * E_C];
        }
        float out4[4];
        #pragma unroll
        for (int u = 0; u < 4; u++) {
            const float kk = kk4[u], vv = vv4[u];

            const float ww = tf + kk;
            const float d  = pp - ww;
            const float m  = __expf(-fabsf(d));
            const float e1 = (d >= 0.f) ? 1.f : m;
            const float e2 = (d >= 0.f) ? m : 1.f;
            out4[u] = tf32r(rr4[u] * __fdividef(e1 * aa + e2 * vv, e1 * bb + e2));

            const float ww2 = dec + pp;
            const float d2  = ww2 - kk;
            const float m2  = __expf(-fabsf(d2));
            const float e1b = (d2 >= 0.f) ? 1.f : m2;
            const float e2b = (d2 >= 0.f) ? m2 : 1.f;
            aa = e1b * aa + e2b * vv;
            bb = e1b * bb + e2b;
            pp = (d2 >= 0.f) ? ww2 : kk;
        }
        #pragma unroll
        for (int u = 0; u < 4; u++)
            g_rwkv[base + (size_t)(j + u) * E_C] = out4[u];
    }
}

// ---------------- launch -----------------------------------------------------
extern "C" void kernel_launch(void* const* d_in, const int* in_sizes, int n_in,
                              void* d_out, int out_size) {
    const float* x   = (const float*)d_in[0];
    const float* sx  = (const float*)d_in[1];
    const float* aa  = (const float*)d_in[2];
    const float* bb  = (const float*)d_in[3];
    const float* pp  = (const float*)d_in[4];
    const float* tf  = (const float*)d_in[5];
    const float* td  = (const float*)d_in[6];
    const float* tmk = (const float*)d_in[7];
    const float* tmv = (const float*)d_in[8];
    const float* tmr = (const float*)d_in[9];
    const float* Wk  = (const float*)d_in[10];
    const float* Wv  = (const float*)d_in[11];
    const float* Wr  = (const float*)d_in[12];
    const float* Wo  = (const float*)d_in[13];
    float* out = (float*)d_out;

    cudaFuncSetAttribute(gemm_kvr_kernel,
                         cudaFuncAttributeMaxDynamicSharedMemorySize, GSMEM_BYTES);
    cudaFuncSetAttribute(gemm_out_kernel,
                         cudaFuncAttributeMaxDynamicSharedMemorySize, GSMEM_BYTES);

    // 1) token-shift mixes (tf32-rounded)
    {
        const int n4 = T_C * E_C / 4;
        mix_kernel<<<(n4 + 255) / 256, 256>>>(x, sx, tmk, tmv, tmr);
    }

    // 2) weight transposes -> [N,K] K-major, tf32-rounded
    transpose_kernel<<<dim3(32, 32, 4), dim3(32, 8)>>>(Wk, Wv, Wr, Wo);

    // 3) merged k, v, r GEMMs (HMMA tf32)
    gemm_kvr_kernel<<<dim3(E_C / 128, T_C / 128, 3), 256, GSMEM_BYTES>>>();

    // 4) segment-parallel WKV scan
    const int write_tail = (out_size >= T_C * E_C + 4 * E_C) ? 1 : 0;
    dim3 sgrid(E_C / 256, SEG);
    scanA_kernel<<<sgrid, 256>>>(td);
    scanB_kernel<<<4, 256>>>(aa, bb, pp, td, x, out, write_tail);
    scanC_kernel<<<sgrid, 256>>>(tf, td);

    // 5) out = x + rwkv @ Wo
    gemm_out_kernel<<<dim3(E_C / 128, T_C / 128), 256, GSMEM_BYTES>>>(out, x);
}